// round 13
// baseline (speedup 1.0000x reference)
#include <cuda_runtime.h>
#include <math.h>
#include <cstdint>

#define NN 100000
#define NE 600000
#define CC 128
#define NL 3
#define NS 10

// ---- f32 scratch ----
__device__ __align__(16) float g_m  [NN * CC];
__device__ __align__(16) float g_agg[NN * CC];
__device__ __align__(16) float g_gi [NN * 3 * CC];
__device__ __align__(16) float g_gh [NN * 3 * CC];
// ---- int8 limb planes + scales ----
__device__ __align__(16) int8_t g_hl  [4 * NN * CC];
__device__ __align__(16) int8_t g_aggl[4 * NN * CC];
__device__ float g_hs [NN];
__device__ float g_aggs[NN];
__device__ __align__(16) int8_t g_wsl[30 * 4 * CC * CC];   // per-step weights
__device__ float g_wss[30 * CC];
__device__ __align__(16) int8_t g_wil[NL * 4 * 3 * CC * CC];
__device__ float g_wis[NL * 3 * CC];
__device__ __align__(16) int8_t g_whl[NL * 4 * 3 * CC * CC];
__device__ float g_whs[NL * 3 * CC];
__device__ int g_src[NE];
__device__ int g_dst[NE];
__device__ int g_is64;

// ============================================================================
// Edge-index normalization (int64-vs-int32 sniffing)
// ============================================================================
__global__ void detect_k(const int* __restrict__ raw) {
    int is64 = 1;
    for (int k = 0; k < 1024; k++) {
        int lo = raw[2 * k], hi = raw[2 * k + 1];
        if (hi != 0 || lo < 0 || lo >= NN) { is64 = 0; break; }
    }
    g_is64 = is64;
}
__global__ void convert_k(const int* __restrict__ raw) {
    int e = blockIdx.x * blockDim.x + threadIdx.x;
    if (e >= NE) return;
    int s, d;
    if (g_is64) { s = raw[2 * e]; d = raw[2 * (NE + e)]; }
    else        { s = raw[e];     d = raw[NE + e]; }
    g_src[e] = min(max(s, 0), NN - 1);
    g_dst[e] = min(max(d, 0), NN - 1);
}

// ============================================================================
// Quantizers: v = s * t / C0,  C0 = 2^28*127/128 = 266338304
//   t = l0*2^21 + l1*2^14 + l2*2^7 + l3 ; l0 in [-127,127], l1..l3 in [-64,64]
// Exact integer split, products exact in s32 imma.
// ============================================================================

// warp-per-row quantizer (row-major [nrows,128] source)
__global__ void quant_rows_k(const float* __restrict__ src, int nrows,
                             int8_t* __restrict__ dst, int pstride,
                             float* __restrict__ scale)
{
    int row = blockIdx.x * 8 + (threadIdx.x >> 5);
    if (row >= nrows) return;
    int lane = threadIdx.x & 31;
    float4 v = *(const float4*)(src + (size_t)row * 128 + lane * 4);
    float m = fmaxf(fmaxf(fabsf(v.x), fabsf(v.y)), fmaxf(fabsf(v.z), fabsf(v.w)));
    #pragma unroll
    for (int o = 16; o > 0; o >>= 1) m = fmaxf(m, __shfl_xor_sync(0xffffffffu, m, o));
    m = fmaxf(m, 1e-35f);
    if (lane == 0) scale[row] = m;
    double inv = 266338304.0 / (double)m;
    float vv[4] = {v.x, v.y, v.z, v.w};
    char4 P0, P1, P2, P3;
    int8_t* p0 = (int8_t*)&P0; int8_t* p1 = (int8_t*)&P1;
    int8_t* p2 = (int8_t*)&P2; int8_t* p3 = (int8_t*)&P3;
    #pragma unroll
    for (int i = 0; i < 4; i++) {
        long long tl = llrint((double)vv[i] * inv);
        int t  = (int)tl;
        int l0 = (t + (1 << 20)) >> 21; int r = t - (l0 << 21);
        int l1 = (r + (1 << 13)) >> 14; r -= (l1 << 14);
        int l2 = (r + (1 << 6))  >> 7;  int l3 = r - (l2 << 7);
        p0[i] = (int8_t)l0; p1[i] = (int8_t)l1; p2[i] = (int8_t)l2; p3[i] = (int8_t)l3;
    }
    size_t base = (size_t)row * 128 + lane * 4;
    *(char4*)(dst + 0 * (size_t)pstride + base) = P0;
    *(char4*)(dst + 1 * (size_t)pstride + base) = P1;
    *(char4*)(dst + 2 * (size_t)pstride + base) = P2;
    *(char4*)(dst + 3 * (size_t)pstride + base) = P3;
}

// warp-per-column quantizer (source [128][128] row-major (k,j); quantize
// column j over k; store limbs as [plane][j][k])
__global__ void quant_cols_k(const float* __restrict__ src,
                             int8_t* __restrict__ dst, int pstride,
                             float* __restrict__ scale)
{
    int j = blockIdx.x * 8 + (threadIdx.x >> 5);
    if (j >= 128) return;
    int lane = threadIdx.x & 31;
    float vv[4];
    #pragma unroll
    for (int i = 0; i < 4; i++) vv[i] = src[(size_t)(lane * 4 + i) * 128 + j];
    float m = fmaxf(fmaxf(fabsf(vv[0]), fabsf(vv[1])), fmaxf(fabsf(vv[2]), fabsf(vv[3])));
    #pragma unroll
    for (int o = 16; o > 0; o >>= 1) m = fmaxf(m, __shfl_xor_sync(0xffffffffu, m, o));
    m = fmaxf(m, 1e-35f);
    if (lane == 0) scale[j] = m;
    double inv = 266338304.0 / (double)m;
    char4 P0, P1, P2, P3;
    int8_t* p0 = (int8_t*)&P0; int8_t* p1 = (int8_t*)&P1;
    int8_t* p2 = (int8_t*)&P2; int8_t* p3 = (int8_t*)&P3;
    #pragma unroll
    for (int i = 0; i < 4; i++) {
        long long tl = llrint((double)vv[i] * inv);
        int t  = (int)tl;
        int l0 = (t + (1 << 20)) >> 21; int r = t - (l0 << 21);
        int l1 = (r + (1 << 13)) >> 14; r -= (l1 << 14);
        int l2 = (r + (1 << 6))  >> 7;  int l3 = r - (l2 << 7);
        p0[i] = (int8_t)l0; p1[i] = (int8_t)l1; p2[i] = (int8_t)l2; p3[i] = (int8_t)l3;
    }
    size_t base = (size_t)j * 128 + lane * 4;
    *(char4*)(dst + 0 * (size_t)pstride + base) = P0;
    *(char4*)(dst + 1 * (size_t)pstride + base) = P1;
    *(char4*)(dst + 2 * (size_t)pstride + base) = P2;
    *(char4*)(dst + 3 * (size_t)pstride + base) = P3;
}

// ============================================================================
// Exact int8-limb GEMM via mma.sync.m16n8k32.s8.s8.s32.
// t_a*t_b = 2^21 * (S0*2^21 + S1*2^14 + S2*2^7 + S3)  [kept terms i+j<=3]
// => OUT = s_a*s_b * f * 2^21/C0^2  (+bias)           *** SC fixed (R12 bug:
// used 2^42/C0^2, a 2^21 overshoot -> rel_err 1.8) ***
// CTA 128n x 64j x 128k; 256 thr; warps 4(m) x 2(n); warp tile 32x32.
// ============================================================================
#define SMA_PL 18432
#define SMB_PL 9216
#define SMB_OFF 73728
#define SMEM_I8 110592

#define IMMA(c, a, b) \
    asm volatile("mma.sync.aligned.m16n8k32.row.col.s32.s8.s8.s32 " \
        "{%0,%1,%2,%3}, {%4,%5,%6,%7}, {%8,%9}, {%0,%1,%2,%3};" \
        : "+r"((c)[0]), "+r"((c)[1]), "+r"((c)[2]), "+r"((c)[3]) \
        : "r"((a)[0]), "r"((a)[1]), "r"((a)[2]), "r"((a)[3]), \
          "r"((b)[0]), "r"((b)[1]))

template<bool HAS_BIAS>
__global__ __launch_bounds__(256, 1)
void i8gemm_k(const int8_t* __restrict__ Al, const float* __restrict__ Asc, int psA,
              const int8_t* __restrict__ Bl, const float* __restrict__ Bsc, int psB,
              const float* __restrict__ bias, float* __restrict__ OUT,
              int Nrows, int Cout)
{
    extern __shared__ char smc[];
    const int tid = threadIdx.x;
    const int n0 = blockIdx.x * 128;
    const int j0 = blockIdx.y * 64;

    // ---- fill A limb planes ----
    #pragma unroll
    for (int i = 0; i < 16; i++) {
        int idx = tid + i * 256;
        int p = idx >> 10, rem = idx & 1023;
        int r = rem >> 3, c = (rem & 7) << 4;
        uint4 v = make_uint4(0u, 0u, 0u, 0u);
        if (n0 + r < Nrows)
            v = *(const uint4*)(Al + (size_t)p * psA + (size_t)(n0 + r) * 128 + c);
        *(uint4*)(smc + p * SMA_PL + r * 144 + c) = v;
    }
    // ---- fill B limb planes ----
    #pragma unroll
    for (int i = 0; i < 8; i++) {
        int idx = tid + i * 256;
        int p = idx >> 9, rem = idx & 511;
        int r = rem >> 3, c = (rem & 7) << 4;
        uint4 v = *(const uint4*)(Bl + (size_t)p * psB + (size_t)(j0 + r) * 128 + c);
        *(uint4*)(smc + SMB_OFF + p * SMB_PL + r * 144 + c) = v;
    }
    __syncthreads();

    const int wid = tid >> 5, lane = tid & 31;
    const int wm = (wid & 3) * 32, wn = (wid >> 2) * 32;
    const int fr = lane >> 2, fc = (lane & 3) * 4;

    int S0[2][4][4], S1[2][4][4], S2[2][4][4], S3[2][4][4];
    #pragma unroll
    for (int mt = 0; mt < 2; mt++)
        #pragma unroll
        for (int nt = 0; nt < 4; nt++)
            #pragma unroll
            for (int q = 0; q < 4; q++) {
                S0[mt][nt][q] = 0; S1[mt][nt][q] = 0;
                S2[mt][nt][q] = 0; S3[mt][nt][q] = 0;
            }

    #pragma unroll
    for (int ks = 0; ks < 4; ks++) {
        const int k0 = ks * 32;
        uint32_t aa[4][2][4];
        #pragma unroll
        for (int p = 0; p < 4; p++)
            #pragma unroll
            for (int mt = 0; mt < 2; mt++) {
                int base = p * SMA_PL + (wm + mt * 16 + fr) * 144 + k0 + fc;
                aa[p][mt][0] = *(const uint32_t*)(smc + base);
                aa[p][mt][1] = *(const uint32_t*)(smc + base + 1152);
                aa[p][mt][2] = *(const uint32_t*)(smc + base + 16);
                aa[p][mt][3] = *(const uint32_t*)(smc + base + 1168);
            }
        uint32_t bb[4][4][2];
        #pragma unroll
        for (int p = 0; p < 4; p++)
            #pragma unroll
            for (int nt = 0; nt < 4; nt++) {
                int base = SMB_OFF + p * SMB_PL + (wn + nt * 8 + fr) * 144 + k0 + fc;
                bb[p][nt][0] = *(const uint32_t*)(smc + base);
                bb[p][nt][1] = *(const uint32_t*)(smc + base + 16);
            }
        #pragma unroll
        for (int mt = 0; mt < 2; mt++)
            #pragma unroll
            for (int nt = 0; nt < 4; nt++) {
                IMMA(S0[mt][nt], aa[0][mt], bb[0][nt]);
                IMMA(S1[mt][nt], aa[0][mt], bb[1][nt]);
                IMMA(S1[mt][nt], aa[1][mt], bb[0][nt]);
                IMMA(S2[mt][nt], aa[0][mt], bb[2][nt]);
                IMMA(S2[mt][nt], aa[1][mt], bb[1][nt]);
                IMMA(S2[mt][nt], aa[2][mt], bb[0][nt]);
                IMMA(S3[mt][nt], aa[0][mt], bb[3][nt]);
                IMMA(S3[mt][nt], aa[1][mt], bb[2][nt]);
                IMMA(S3[mt][nt], aa[2][mt], bb[1][nt]);
                IMMA(S3[mt][nt], aa[3][mt], bb[0][nt]);
            }
    }

    // ---- epilogue: SC = 2^21 / C0^2  (FIXED) ----
    const float SC = (float)(2097152.0 / (266338304.0 * 266338304.0));
    const int ecol = (lane & 3) * 2;
    #pragma unroll
    for (int mt = 0; mt < 2; mt++)
        #pragma unroll
        for (int half = 0; half < 2; half++) {
            int gr = n0 + wm + mt * 16 + half * 8 + fr;
            if (gr >= Nrows) continue;
            float sa = Asc[gr] * SC;
            float* orow = OUT + (size_t)gr * Cout + j0;
            #pragma unroll
            for (int nt = 0; nt < 4; nt++) {
                int c = wn + nt * 8 + ecol;
                int q = half * 2;
                float f0 = fmaf((float)S0[mt][nt][q], 2097152.f,
                           fmaf((float)S1[mt][nt][q], 16384.f,
                           fmaf((float)S2[mt][nt][q], 128.f, (float)S3[mt][nt][q])));
                float f1 = fmaf((float)S0[mt][nt][q+1], 2097152.f,
                           fmaf((float)S1[mt][nt][q+1], 16384.f,
                           fmaf((float)S2[mt][nt][q+1], 128.f, (float)S3[mt][nt][q+1])));
                float2 o;
                o.x = f0 * (sa * Bsc[j0 + c]);
                o.y = f1 * (sa * Bsc[j0 + c + 1]);
                if (HAS_BIAS) { o.x += bias[j0 + c]; o.y += bias[j0 + c + 1]; }
                *(float2*)(orow + c) = o;
            }
        }
}

// ============================================================================
// Edge scatter: agg[dst] += m[src], float4 atomics; 32 threads/edge
// ============================================================================
__global__ void scatter_k(const float* __restrict__ m, float* __restrict__ agg)
{
    long long t = (long long)blockIdx.x * blockDim.x + threadIdx.x;
    int e = (int)(t >> 5);
    if (e >= NE) return;
    int c = ((int)t & 31) << 2;
    int s = g_src[e];
    int d = g_dst[e];
    float4 v = *(const float4*)(m + (size_t)s * CC + c);
    atomicAdd((float4*)(agg + (size_t)d * CC + c), v);
}

// ============================================================================
// GRU gate: h = (1-z)*tanh(i_n + r*h_n) + z*h ; optional ReLU
// ============================================================================
__global__ void gate_k(const float* __restrict__ gi, const float* __restrict__ gh,
                       float* __restrict__ h, int relu)
{
    int t = blockIdx.x * blockDim.x + threadIdx.x;
    if (t >= NN * CC) return;
    int n = t >> 7;
    int j = t & 127;
    const float* gin = gi + (size_t)n * 384;
    const float* ghn = gh + (size_t)n * 384;
    float i_r = gin[j], i_z = gin[128 + j], i_n = gin[256 + j];
    float h_r = ghn[j], h_z = ghn[128 + j], h_n = ghn[256 + j];
    float hv = h[t];
    float r = 1.f / (1.f + __expf(-(i_r + h_r)));
    float z = 1.f / (1.f + __expf(-(i_z + h_z)));
    float nn = tanhf(i_n + r * h_n);
    float o = (1.f - z) * nn + z * hv;
    if (relu) o = fmaxf(o, 0.f);
    h[t] = o;
}

// ============================================================================
extern "C" void kernel_launch(void* const* d_in, const int* in_sizes, int n_in,
                              void* d_out, int out_size)
{
    const float* x       = (const float*)d_in[0];
    const int*   ei_raw  = (const int*)d_in[1];
    const float* weights = (const float*)d_in[2];
    const float* w_ih    = (const float*)d_in[3];
    const float* w_hh    = (const float*)d_in[4];
    const float* b_ih    = (const float*)d_in[5];
    const float* b_hh    = (const float*)d_in[6];
    float* h = (float*)d_out;

    void *pm, *pagg, *pgi, *pgh, *phl, *phs, *paggl, *paggs;
    void *pwsl, *pwss, *pwil, *pwis, *pwhl, *pwhs;
    cudaGetSymbolAddress(&pm,    g_m);
    cudaGetSymbolAddress(&pagg,  g_agg);
    cudaGetSymbolAddress(&pgi,   g_gi);
    cudaGetSymbolAddress(&pgh,   g_gh);
    cudaGetSymbolAddress(&phl,   g_hl);
    cudaGetSymbolAddress(&phs,   g_hs);
    cudaGetSymbolAddress(&paggl, g_aggl);
    cudaGetSymbolAddress(&paggs, g_aggs);
    cudaGetSymbolAddress(&pwsl,  g_wsl);
    cudaGetSymbolAddress(&pwss,  g_wss);
    cudaGetSymbolAddress(&pwil,  g_wil);
    cudaGetSymbolAddress(&pwis,  g_wis);
    cudaGetSymbolAddress(&pwhl,  g_whl);
    cudaGetSymbolAddress(&pwhs,  g_whs);

    cudaFuncSetAttribute(i8gemm_k<false>,
                         cudaFuncAttributeMaxDynamicSharedMemorySize, SMEM_I8);
    cudaFuncSetAttribute(i8gemm_k<true>,
                         cudaFuncAttributeMaxDynamicSharedMemorySize, SMEM_I8);

    detect_k<<<1, 1>>>(ei_raw);
    convert_k<<<(NE + 255) / 256, 256>>>(ei_raw);

    // ---- quantize all weights once ----
    for (int l = 0; l < NL; l++) {
        quant_rows_k<<<(3 * CC + 7) / 8, 256>>>(
            w_ih + (size_t)l * 3 * CC * CC, 3 * CC,
            (int8_t*)pwil + (size_t)l * 4 * 3 * CC * CC, 3 * CC * CC,
            (float*)pwis + (size_t)l * 3 * CC);
        quant_rows_k<<<(3 * CC + 7) / 8, 256>>>(
            w_hh + (size_t)l * 3 * CC * CC, 3 * CC,
            (int8_t*)pwhl + (size_t)l * 4 * 3 * CC * CC, 3 * CC * CC,
            (float*)pwhs + (size_t)l * 3 * CC);
    }
    for (int t = 0; t < NL * NS; t++) {
        quant_cols_k<<<16, 256>>>(
            weights + (size_t)t * CC * CC,
            (int8_t*)pwsl + (size_t)t * 4 * CC * CC, CC * CC,
            (float*)pwss + (size_t)t * CC);
    }

    // h <- x
    cudaMemcpyAsync(h, x, sizeof(float) * (size_t)NN * CC,
                    cudaMemcpyDeviceToDevice);

    const int NB = (NN + 127) / 128;  // 782

    for (int l = 0; l < NL; l++) {
        const float* bi = b_ih + (size_t)l * 3 * CC;
        const float* bh = b_hh + (size_t)l * 3 * CC;
        for (int s = 0; s < NS; s++) {
            int t = l * NS + s;

            // quantize h
            quant_rows_k<<<(NN + 7) / 8, 256>>>(
                h, NN, (int8_t*)phl, NN * CC, (float*)phs);

            // m = h @ w_step
            i8gemm_k<false><<<dim3(NB, 2), 256, SMEM_I8>>>(
                (const int8_t*)phl, (const float*)phs, NN * CC,
                (const int8_t*)pwsl + (size_t)t * 4 * CC * CC,
                (const float*)pwss + (size_t)t * CC, CC * CC,
                nullptr, (float*)pm, NN, CC);

            // agg = segment_sum(m[src], dst)
            cudaMemsetAsync(pagg, 0, sizeof(float) * (size_t)NN * CC);
            scatter_k<<<(int)(((long long)NE * 32 + 255) / 256), 256>>>(
                (const float*)pm, (float*)pagg);

            // quantize agg
            quant_rows_k<<<(NN + 7) / 8, 256>>>(
                (const float*)pagg, NN, (int8_t*)paggl, NN * CC, (float*)paggs);

            // gi = agg @ wi^T + bi
            i8gemm_k<true><<<dim3(NB, 6), 256, SMEM_I8>>>(
                (const int8_t*)paggl, (const float*)paggs, NN * CC,
                (const int8_t*)pwil + (size_t)l * 4 * 3 * CC * CC,
                (const float*)pwis + (size_t)l * 3 * CC, 3 * CC * CC,
                bi, (float*)pgi, NN, 3 * CC);

            // gh = h @ wh^T + bh
            i8gemm_k<true><<<dim3(NB, 6), 256, SMEM_I8>>>(
                (const int8_t*)phl, (const float*)phs, NN * CC,
                (const int8_t*)pwhl + (size_t)l * 4 * 3 * CC * CC,
                (const float*)pwhs + (size_t)l * 3 * CC, 3 * CC * CC,
                bh, (float*)pgh, NN, 3 * CC);

            int relu = (s == NS - 1 && l < NL - 1) ? 1 : 0;
            gate_k<<<(NN * CC + 255) / 256, 256>>>(
                (const float*)pgi, (const float*)pgh, h, relu);
        }
    }
}

// round 15
// speedup vs baseline: 2.8958x; 2.8958x over previous
#include <cuda_runtime.h>
#include <math.h>
#include <cstdint>

#define NN 100000
#define NE 600000
#define CC 128
#define NL 3
#define NS 10

// Scratch (allocation-free rule: __device__ globals), 16B-aligned.
__device__ __align__(16) float g_m  [NN * CC];
__device__ __align__(16) float g_agg[NN * CC];
__device__ __align__(16) float g_gi [NN * 3 * CC];
__device__ __align__(16) float g_gh [NN * 3 * CC];
__device__ int g_src[NE];
__device__ int g_dst[NE];
__device__ int g_esrc[NE];      // CSR: src indices grouped by dst
__device__ int g_off[NN + 1];   // CSR row offsets
__device__ int g_deg[NN];
__device__ int g_cur[NN];
__device__ int g_is64;

// ============================================================================
// Edge-index normalization (int64-vs-int32 sniffing)
// ============================================================================
__global__ void detect_k(const int* __restrict__ raw) {
    int is64 = 1;
    for (int k = 0; k < 1024; k++) {
        int lo = raw[2 * k], hi = raw[2 * k + 1];
        if (hi != 0 || lo < 0 || lo >= NN) { is64 = 0; break; }
    }
    g_is64 = is64;
}
__global__ void convert_k(const int* __restrict__ raw) {
    int e = blockIdx.x * blockDim.x + threadIdx.x;
    if (e >= NE) return;
    int s, d;
    if (g_is64) { s = raw[2 * e]; d = raw[2 * (NE + e)]; }
    else        { s = raw[e];     d = raw[NE + e]; }
    g_src[e] = min(max(s, 0), NN - 1);
    g_dst[e] = min(max(d, 0), NN - 1);
}

// ============================================================================
// CSR build (once per call; edges static across steps)
// ============================================================================
__global__ void count_k() {
    int e = blockIdx.x * blockDim.x + threadIdx.x;
    if (e >= NE) return;
    atomicAdd(&g_deg[g_dst[e]], 1);
}

__global__ void scan_k() {
    __shared__ int warp_s[32];
    const int tid = threadIdx.x;
    const int CH = (NN + 1023) / 1024;           // 98
    int start = tid * CH;
    int end = min(start + CH, NN);
    int s = 0;
    for (int i = start; i < end; i++) s += g_deg[i];
    int lane = tid & 31, wid = tid >> 5;
    int v = s;
    #pragma unroll
    for (int o = 1; o < 32; o <<= 1) {
        int t = __shfl_up_sync(0xffffffffu, v, o);
        if (lane >= o) v += t;
    }
    if (lane == 31) warp_s[wid] = v;
    __syncthreads();
    if (wid == 0) {
        int w = warp_s[lane];
        #pragma unroll
        for (int o = 1; o < 32; o <<= 1) {
            int t = __shfl_up_sync(0xffffffffu, w, o);
            if (lane >= o) w += t;
        }
        warp_s[lane] = w;
    }
    __syncthreads();
    int excl = (v - s) + (wid > 0 ? warp_s[wid - 1] : 0);
    int run = excl;
    for (int i = start; i < end; i++) {
        g_off[i] = run;
        g_cur[i] = run;
        run += g_deg[i];
    }
    if (tid == 0) g_off[NN] = NE;
}

__global__ void fill_k() {
    int e = blockIdx.x * blockDim.x + threadIdx.x;
    if (e >= NE) return;
    int d = g_dst[e];
    int pos = atomicAdd(&g_cur[d], 1);
    g_esrc[pos] = g_src[e];
}

// ============================================================================
// Packed-fp32 SGEMM via fma.rn.f32x2 (R7 kernel, proven).
// OUT[n,j] = sum_k IN[n,k] * W(j,k) (+ bias[j])
//   WT=true : W [Cout,128] row-major, W(j,k)=W[j*128+k]
//   WT=false: W [128,Cout] row-major, W(j,k)=W[k*Cout+j]
// CTA: 128n x 128j x 128k, 256 threads, 8x8 micro-tile per thread.
// ============================================================================
#define SMEM_TOT (2 * 128 * 128 * 4)   // 128 KB

typedef unsigned long long u64;

__device__ __forceinline__ u64 packf2(float x, float y) {
    u64 r;
    asm("mov.b64 %0, {%1, %2};" : "=l"(r) : "f"(x), "f"(y));
    return r;
}
__device__ __forceinline__ void unpackf2(u64 p, float& x, float& y) {
    asm("mov.b64 {%0, %1}, %2;" : "=f"(x), "=f"(y) : "l"(p));
}
#define FMA2(c, a, b) \
    asm("fma.rn.f32x2 %0, %1, %2, %0;" : "+l"(c) : "l"(a), "l"(b))

template<bool WT, bool HAS_BIAS>
__global__ __launch_bounds__(256, 1)
void gemm2_k(const float* __restrict__ IN, const float* __restrict__ W,
             const float* __restrict__ bias, float* __restrict__ OUT,
             int Nrows, int Cout)
{
    extern __shared__ float sm[];
    float* As = sm;                 // [128][128]  As[row*128+k]
    float* Bs = sm + 128 * 128;     // [128][128]  Bs[k*128+j]

    const int tid = threadIdx.x;
    const int n0 = blockIdx.x * 128;
    const int j0 = blockIdx.y * 128;

    #pragma unroll
    for (int i = tid; i < 128 * 32; i += 256) {
        int row = i >> 5;
        int kc  = (i & 31) << 2;
        float4 v = make_float4(0.f, 0.f, 0.f, 0.f);
        int gr = n0 + row;
        if (gr < Nrows) v = *(const float4*)(IN + (size_t)gr * CC + kc);
        *(float4*)(As + row * 128 + kc) = v;
    }

    if (WT) {
        #pragma unroll
        for (int i = tid; i < 128 * 32; i += 256) {
            int j  = i & 127;
            int kc = (i >> 7) << 2;
            float4 v = *(const float4*)(W + (size_t)(j0 + j) * 128 + kc);
            Bs[(kc + 0) * 128 + j] = v.x;
            Bs[(kc + 1) * 128 + j] = v.y;
            Bs[(kc + 2) * 128 + j] = v.z;
            Bs[(kc + 3) * 128 + j] = v.w;
        }
    } else {
        #pragma unroll
        for (int i = tid; i < 128 * 32; i += 256) {
            int k  = i >> 5;
            int jc = (i & 31) << 2;
            float4 v = *(const float4*)(W + (size_t)k * Cout + j0 + jc);
            *(float4*)(Bs + k * 128 + jc) = v;
        }
    }
    __syncthreads();

    const int tx = tid & 15, ty = tid >> 4;
    const int nt = ty * 8, jt = tx * 8;

    u64 acc[8][4];
    #pragma unroll
    for (int i = 0; i < 8; i++)
        #pragma unroll
        for (int jp = 0; jp < 4; jp++) acc[i][jp] = 0ull;

    #pragma unroll 4
    for (int k = 0; k < 128; k++) {
        float4 b0 = *(const float4*)(Bs + k * 128 + jt);
        float4 b1 = *(const float4*)(Bs + k * 128 + jt + 4);
        u64 bp[4];
        bp[0] = packf2(b0.x, b0.y);
        bp[1] = packf2(b0.z, b0.w);
        bp[2] = packf2(b1.x, b1.y);
        bp[3] = packf2(b1.z, b1.w);
        u64 ad[8];
        #pragma unroll
        for (int i = 0; i < 8; i++) {
            float a = As[(nt + i) * 128 + k];
            ad[i] = packf2(a, a);
        }
        #pragma unroll
        for (int i = 0; i < 8; i++)
            #pragma unroll
            for (int jp = 0; jp < 4; jp++)
                FMA2(acc[i][jp], ad[i], bp[jp]);
    }

    float bv[8];
    if (HAS_BIAS) {
        #pragma unroll
        for (int j = 0; j < 8; j++) bv[j] = bias[j0 + jt + j];
    }
    #pragma unroll
    for (int i = 0; i < 8; i++) {
        int gr = n0 + nt + i;
        if (gr >= Nrows) continue;
        float o[8];
        #pragma unroll
        for (int jp = 0; jp < 4; jp++)
            unpackf2(acc[i][jp], o[2 * jp], o[2 * jp + 1]);
        if (HAS_BIAS) {
            #pragma unroll
            for (int j = 0; j < 8; j++) o[j] += bv[j];
        }
        float* op = OUT + (size_t)gr * Cout + j0 + jt;
        *(float4*)(op)     = make_float4(o[0], o[1], o[2], o[3]);
        *(float4*)(op + 4) = make_float4(o[4], o[5], o[6], o[7]);
    }
}

// ============================================================================
// CSR gather aggregation: agg[d] = sum_{e in CSR[d]} m[esrc[e]]
// warp per dst row, lane per float4 column; no atomics, no memset.
// ============================================================================
__global__ void gather_k(const float* __restrict__ m, float* __restrict__ agg)
{
    int d = blockIdx.x * 8 + (threadIdx.x >> 5);
    if (d >= NN) return;
    int lane = threadIdx.x & 31;
    int beg = g_off[d], end = g_off[d + 1];
    float4 acc = make_float4(0.f, 0.f, 0.f, 0.f);
    for (int e = beg; e < end; e++) {
        int s = g_esrc[e];
        float4 v = *(const float4*)(m + (size_t)s * CC + lane * 4);
        acc.x += v.x; acc.y += v.y; acc.z += v.z; acc.w += v.w;
    }
    *(float4*)(agg + (size_t)d * CC + lane * 4) = acc;
}

// ============================================================================
// GRU gate: h = (1-z)*tanh(i_n + r*h_n) + z*h ; optional ReLU
// ============================================================================
__global__ void gate_k(const float* __restrict__ gi, const float* __restrict__ gh,
                       float* __restrict__ h, int relu)
{
    int t = blockIdx.x * blockDim.x + threadIdx.x;
    if (t >= NN * CC) return;
    int n = t >> 7;
    int j = t & 127;
    const float* gin = gi + (size_t)n * 384;
    const float* ghn = gh + (size_t)n * 384;
    float i_r = gin[j], i_z = gin[128 + j], i_n = gin[256 + j];
    float h_r = ghn[j], h_z = ghn[128 + j], h_n = ghn[256 + j];
    float hv = h[t];
    float r = 1.f / (1.f + __expf(-(i_r + h_r)));
    float z = 1.f / (1.f + __expf(-(i_z + h_z)));
    float nn = tanhf(i_n + r * h_n);
    float o = (1.f - z) * nn + z * hv;
    if (relu) o = fmaxf(o, 0.f);
    h[t] = o;
}

// ============================================================================
extern "C" void kernel_launch(void* const* d_in, const int* in_sizes, int n_in,
                              void* d_out, int out_size)
{
    const float* x       = (const float*)d_in[0];
    const int*   ei_raw  = (const int*)d_in[1];
    const float* weights = (const float*)d_in[2];
    const float* w_ih    = (const float*)d_in[3];
    const float* w_hh    = (const float*)d_in[4];
    const float* b_ih    = (const float*)d_in[5];
    const float* b_hh    = (const float*)d_in[6];
    float* h = (float*)d_out;

    void *pm, *pagg, *pgi, *pgh, *pdeg;
    cudaGetSymbolAddress(&pm,   g_m);
    cudaGetSymbolAddress(&pagg, g_agg);
    cudaGetSymbolAddress(&pgi,  g_gi);
    cudaGetSymbolAddress(&pgh,  g_gh);
    cudaGetSymbolAddress(&pdeg, g_deg);

    cudaFuncSetAttribute(gemm2_k<false, false>,
                         cudaFuncAttributeMaxDynamicSharedMemorySize, SMEM_TOT);
    cudaFuncSetAttribute(gemm2_k<true, true>,
                         cudaFuncAttributeMaxDynamicSharedMemorySize, SMEM_TOT);

    // ---- edge normalization + CSR build (once per call) ----
    detect_k<<<1, 1>>>(ei_raw);
    convert_k<<<(NE + 255) / 256, 256>>>(ei_raw);
    cudaMemsetAsync(pdeg, 0, sizeof(int) * NN);
    count_k<<<(NE + 255) / 256, 256>>>();
    scan_k<<<1, 1024>>>();
    fill_k<<<(NE + 255) / 256, 256>>>();

    // h <- x
    cudaMemcpyAsync(h, x, sizeof(float) * (size_t)NN * CC,
                    cudaMemcpyDeviceToDevice);

    const int NB = (NN + 127) / 128;  // 782

    for (int l = 0; l < NL; l++) {
        const float* wi = w_ih + (size_t)l * 3 * CC * CC;
        const float* wh = w_hh + (size_t)l * 3 * CC * CC;
        const float* bi = b_ih + (size_t)l * 3 * CC;
        const float* bh = b_hh + (size_t)l * 3 * CC;
        for (int s = 0; s < NS; s++) {
            const float* w = weights + ((size_t)l * NS + s) * CC * CC;

            // m = h @ w
            gemm2_k<false, false><<<dim3(NB, 1), 256, SMEM_TOT>>>(
                h, w, nullptr, (float*)pm, NN, CC);

            // agg = segment_sum(m[src], dst)  — CSR gather, no atomics/memset
            gather_k<<<(NN + 7) / 8, 256>>>((const float*)pm, (float*)pagg);

            // gi = agg @ wi^T + bi ; gh = h @ wh^T + bh
            gemm2_k<true, true><<<dim3(NB, 3), 256, SMEM_TOT>>>(
                (const float*)pagg, wi, bi, (float*)pgi, NN, 3 * CC);
            gemm2_k<true, true><<<dim3(NB, 3), 256, SMEM_TOT>>>(
                h, wh, bh, (float*)pgh, NN, 3 * CC);

            int relu = (s == NS - 1 && l < NL - 1) ? 1 : 0;
            gate_k<<<(NN * CC + 255) / 256, 256>>>(
                (const float*)pgi, (const float*)pgh, h, relu);
        }
    }
}